// round 5
// baseline (speedup 1.0000x reference)
#include <cuda_runtime.h>

#define NB   16
#define NF   64
#define LATD 512
#define IMG  64
#define HWD  4096
#define FIN  576
#define PD   78016
#define CATD 2048

#define OFF_KIN  0
#define OFF_BIN  36864
#define OFF_KOUT 36928
#define OFF_BOUT 41024
#define OFF_KSK  41088
#define OFF_BSK  77952

// ---------------- scratch (device globals; no allocs allowed) ----------------
__device__ float g_out [NB*NF*HWD];          // 16.8 MB
__device__ float g_feat[(size_t)NB*FIN*HWD]; // 151 MB
__device__ float g_h   [NB*NF*HWD];          // 16.8 MB
__device__ float g_p   [NB*PD];              // 5 MB
__device__ float g_injA[NB*LATD], g_injB[NB*LATD];
__device__ float g_latA[NB*LATD], g_latB[NB*LATD];
__device__ float g_t512[NB*LATD];
__device__ float g_cat [NB*CATD];
__device__ float g_t2048[NB*CATD];
__device__ float g_part[16*NB*CATD];         // K-split partial sums

__device__ __forceinline__ float lrelu(float v){ return v > 0.f ? v : 0.2f*v; }

// ---------------- out0 = w_in @ x + b_in ----------------
__global__ void k_init_out(const float* __restrict__ x, const float* __restrict__ w_in,
                           const float* __restrict__ b_in, float* __restrict__ out){
    int b = blockIdx.x >> 6, o = blockIdx.x & 63;
    float w0 = w_in[o*3+0], w1 = w_in[o*3+1], w2 = w_in[o*3+2], bb = b_in[o];
    const float* xb = x + (size_t)b*3*HWD;
    float* ob = out + (size_t)blockIdx.x*HWD;
    for (int p = threadIdx.x; p < HWD; p += blockDim.x)
        ob[p] = w0*xb[p] + w1*xb[HWD+p] + w2*xb[2*HWD+p] + bb;
}

__global__ void k_zero(float* p){ p[blockIdx.x*512 + threadIdx.x] = 0.f; }

__global__ void k_copylat(const float* __restrict__ lat, float* __restrict__ cat){
    int idx = blockIdx.x*256 + threadIdx.x;   // 8192
    int b = idx >> 9, n = idx & 511;
    cat[b*CATD + n] = lat[idx];
}

// ---------------- small GEMMs: Y(16,N) = X(16,K) @ W(K,N) ----------------
// K-split partial kernel (deterministic; reduce kernel sums slots + biases + act).
__global__ void __launch_bounds__(128) gemm16_part(
    const float* __restrict__ X, int K, const float* __restrict__ W,
    float* __restrict__ Yp, int N, int kc, int slot0)
{
    __shared__ __align__(16) float Xs[256*16];
    int ks = blockIdx.y;
    int k0 = ks*kc;
    int klen = min(kc, K - k0);
    for (int k = threadIdx.x; k < klen; k += 128){
        #pragma unroll
        for (int b = 0; b < 16; b++) Xs[k*16+b] = X[(size_t)b*K + k0 + k];
    }
    __syncthreads();
    int n = blockIdx.x*128 + threadIdx.x;
    if (n >= N) return;
    float acc[16];
    #pragma unroll
    for (int b = 0; b < 16; b++) acc[b] = 0.f;
    #pragma unroll 4
    for (int k = 0; k < klen; k++){
        float w = W[(size_t)(k0+k)*N + n];
        const float4* xp = (const float4*)(Xs + k*16);
        float4 x0 = xp[0], x1 = xp[1], x2 = xp[2], x3 = xp[3];
        acc[0]+=x0.x*w; acc[1]+=x0.y*w; acc[2]+=x0.z*w; acc[3]+=x0.w*w;
        acc[4]+=x1.x*w; acc[5]+=x1.y*w; acc[6]+=x1.z*w; acc[7]+=x1.w*w;
        acc[8]+=x2.x*w; acc[9]+=x2.y*w; acc[10]+=x2.z*w; acc[11]+=x2.w*w;
        acc[12]+=x3.x*w; acc[13]+=x3.y*w; acc[14]+=x3.z*w; acc[15]+=x3.w*w;
    }
    float* yp = Yp + (size_t)(slot0+ks)*16*N;
    #pragma unroll
    for (int b = 0; b < 16; b++) yp[(size_t)b*N + n] = acc[b];
}

__global__ void gemm16_reduce(const float* __restrict__ Yp, int nslots,
                              const float* __restrict__ b1, const float* __restrict__ b2,
                              float* __restrict__ Y, int N, int leaky)
{
    int idx = blockIdx.x*256 + threadIdx.x;
    if (idx >= 16*N) return;
    int n = idx % N;
    float s = 0.f;
    for (int t = 0; t < nslots; t++) s += Yp[(size_t)t*16*N + idx];
    if (b1) s += b1[n];
    if (b2) s += b2[n];
    if (leaky) s = lrelu(s);
    Y[idx] = s;
}

// Direct (no split) version with bias — used for p = inj @ dyn_w + dyn_b (N=78016)
__global__ void __launch_bounds__(128) gemm16_full(
    const float* __restrict__ X, int K, const float* __restrict__ W,
    const float* __restrict__ bias, float* __restrict__ Y, int N)
{
    __shared__ __align__(16) float Xs[512*16];
    for (int k = threadIdx.x; k < K; k += 128){
        #pragma unroll
        for (int b = 0; b < 16; b++) Xs[k*16+b] = X[(size_t)b*K + k];
    }
    __syncthreads();
    int n = blockIdx.x*128 + threadIdx.x;
    if (n >= N) return;
    float acc[16];
    #pragma unroll
    for (int b = 0; b < 16; b++) acc[b] = 0.f;
    #pragma unroll 4
    for (int k = 0; k < K; k++){
        float w = W[(size_t)k*N + n];
        const float4* xp = (const float4*)(Xs + k*16);
        float4 x0 = xp[0], x1 = xp[1], x2 = xp[2], x3 = xp[3];
        acc[0]+=x0.x*w; acc[1]+=x0.y*w; acc[2]+=x0.z*w; acc[3]+=x0.w*w;
        acc[4]+=x1.x*w; acc[5]+=x1.y*w; acc[6]+=x1.z*w; acc[7]+=x1.w*w;
        acc[8]+=x2.x*w; acc[9]+=x2.y*w; acc[10]+=x2.z*w; acc[11]+=x2.w*w;
        acc[12]+=x3.x*w; acc[13]+=x3.y*w; acc[14]+=x3.z*w; acc[15]+=x3.w*w;
    }
    float bv = bias[n];
    #pragma unroll
    for (int b = 0; b < 16; b++) Y[(size_t)b*N + n] = acc[b] + bv;
}

// ---------------- perceive (dilated Sobel bank) + instance norm ----------------
__global__ void __launch_bounds__(256) k_perceive(const float* __restrict__ out,
                                                  float* __restrict__ feat){
    __shared__ float xs[64*64];
    __shared__ float rs1[8], rs2[8], bcast[2];
    int bcid = blockIdx.x;
    int b = bcid >> 6, c = bcid & 63;
    const float* src = out + (size_t)bcid*HWD;
    for (int p = threadIdx.x; p < HWD; p += 256) xs[p] = src[p];
    __syncthreads();
    int lane = threadIdx.x & 31, wrp = threadIdx.x >> 5;
    for (int g = 0; g < 9; g++){
        float v[16];
        float s1 = 0.f, s2 = 0.f;
        int d = (g == 0) ? 0 : (1 << ((g-1) >> 1));
        int isX = ((g-1) & 1) == 0;
        #pragma unroll
        for (int t = 0; t < 16; t++){
            int p = threadIdx.x + t*256;
            int i = p >> 6, j = p & 63;
            float val;
            if (g == 0){
                val = xs[p];
            } else {
                int im = i-d, ip = i+d, jm = j-d, jp = j+d;
                bool imv = im >= 0, ipv = ip < 64, jmv = jm >= 0, jpv = jp < 64;
                if (isX){
                    float t0 = ((imv&&jpv) ? xs[im*64+jp] : 0.f) - ((imv&&jmv) ? xs[im*64+jm] : 0.f);
                    float t1 = (jpv ? xs[i*64+jp] : 0.f)         - (jmv ? xs[i*64+jm] : 0.f);
                    float t2 = ((ipv&&jpv) ? xs[ip*64+jp] : 0.f) - ((ipv&&jmv) ? xs[ip*64+jm] : 0.f);
                    val = 0.125f*(t0 + 2.f*t1 + t2);
                } else {
                    float t0 = ((ipv&&jmv) ? xs[ip*64+jm] : 0.f) - ((imv&&jmv) ? xs[im*64+jm] : 0.f);
                    float t1 = (ipv ? xs[ip*64+j] : 0.f)         - (imv ? xs[im*64+j] : 0.f);
                    float t2 = ((ipv&&jpv) ? xs[ip*64+jp] : 0.f) - ((imv&&jpv) ? xs[im*64+jp] : 0.f);
                    val = 0.125f*(t0 + 2.f*t1 + t2);
                }
            }
            v[t] = val; s1 += val; s2 += val*val;
        }
        #pragma unroll
        for (int s = 16; s > 0; s >>= 1){
            s1 += __shfl_xor_sync(0xffffffffu, s1, s);
            s2 += __shfl_xor_sync(0xffffffffu, s2, s);
        }
        if (lane == 0){ rs1[wrp] = s1; rs2[wrp] = s2; }
        __syncthreads();
        if (threadIdx.x == 0){
            float a = 0.f, q = 0.f;
            #pragma unroll
            for (int w = 0; w < 8; w++){ a += rs1[w]; q += rs2[w]; }
            float mean = a*(1.f/4096.f);
            float var  = q*(1.f/4096.f) - mean*mean;
            bcast[0] = mean; bcast[1] = rsqrtf(var + 1e-5f);
        }
        __syncthreads();
        float mean = bcast[0], inv = bcast[1];
        float* dst = feat + ((size_t)b*FIN + g*64 + c)*HWD;
        #pragma unroll
        for (int t = 0; t < 16; t++)
            dst[threadIdx.x + t*256] = (v[t]-mean)*inv;
    }
}

// ---------------- batched 64xN tile GEMMs (dynamic conv) ----------------
#define ASP 68
#define TNN 128
#define KCH 16

__device__ __forceinline__ void tile_phase(
    const float* __restrict__ A, int lda, int K,
    const float* __restrict__ Bm, int n0,
    float* As, float* Bs, float acc[4][8])
{
    int tid = threadIdx.x;
    int tm = tid & 15, tn = tid >> 4;
    int mA = tid >> 2, qA = tid & 3;
    int rB = tid >> 5, cB = (tid & 31) * 4;
    for (int k0 = 0; k0 < K; k0 += KCH){
        float4 av  = *(const float4*)(A + (size_t)mA*lda + k0 + qA*4);
        float4 bv0 = *(const float4*)(Bm + (size_t)(k0 + rB)*HWD     + n0 + cB);
        float4 bv1 = *(const float4*)(Bm + (size_t)(k0 + rB + 8)*HWD + n0 + cB);
        __syncthreads();
        As[(qA*4+0)*ASP + mA] = av.x;
        As[(qA*4+1)*ASP + mA] = av.y;
        As[(qA*4+2)*ASP + mA] = av.z;
        As[(qA*4+3)*ASP + mA] = av.w;
        *(float4*)(Bs + rB*TNN + cB)     = bv0;
        *(float4*)(Bs + (rB+8)*TNN + cB) = bv1;
        __syncthreads();
        #pragma unroll
        for (int k = 0; k < KCH; k++){
            float a0 = As[k*ASP + tm*4 + 0];
            float a1 = As[k*ASP + tm*4 + 1];
            float a2 = As[k*ASP + tm*4 + 2];
            float a3 = As[k*ASP + tm*4 + 3];
            float bb[8];
            #pragma unroll
            for (int j = 0; j < 8; j++) bb[j] = Bs[k*TNN + tn*8 + j];
            #pragma unroll
            for (int j = 0; j < 8; j++){
                acc[0][j] += a0*bb[j];
                acc[1][j] += a1*bb[j];
                acc[2][j] += a2*bb[j];
                acc[3][j] += a3*bb[j];
            }
        }
    }
    __syncthreads();
}

__global__ void __launch_bounds__(256) k_gemm_h(const float* __restrict__ p,
                                                const float* __restrict__ feat,
                                                float* __restrict__ h){
    __shared__ __align__(16) float As[KCH*ASP];
    __shared__ __align__(16) float Bs[KCH*TNN];
    int b = blockIdx.y, n0 = blockIdx.x*TNN;
    const float* pb = p + (size_t)b*PD;
    float acc[4][8];
    #pragma unroll
    for (int r = 0; r < 4; r++)
        #pragma unroll
        for (int j = 0; j < 8; j++) acc[r][j] = 0.f;
    tile_phase(pb + OFF_KIN, FIN, FIN, feat + (size_t)b*FIN*HWD, n0, As, Bs, acc);
    int tm = threadIdx.x & 15, tn = threadIdx.x >> 4;
    #pragma unroll
    for (int r = 0; r < 4; r++){
        int m = tm*4 + r;
        float bias = pb[OFF_BIN + m];
        float* dst = h + ((size_t)b*NF + m)*HWD + n0 + tn*8;
        float4 v0, v1;
        v0.x = lrelu(acc[r][0]+bias); v0.y = lrelu(acc[r][1]+bias);
        v0.z = lrelu(acc[r][2]+bias); v0.w = lrelu(acc[r][3]+bias);
        v1.x = lrelu(acc[r][4]+bias); v1.y = lrelu(acc[r][5]+bias);
        v1.z = lrelu(acc[r][6]+bias); v1.w = lrelu(acc[r][7]+bias);
        *(float4*)dst = v0; *(float4*)(dst+4) = v1;
    }
}

__global__ void __launch_bounds__(256) k_gemm_out(const float* __restrict__ p,
                                                  const float* __restrict__ h,
                                                  const float* __restrict__ feat,
                                                  float* __restrict__ outp){
    __shared__ __align__(16) float As[KCH*ASP];
    __shared__ __align__(16) float Bs[KCH*TNN];
    int b = blockIdx.y, n0 = blockIdx.x*TNN;
    const float* pb = p + (size_t)b*PD;
    float acc[4][8];
    #pragma unroll
    for (int r = 0; r < 4; r++)
        #pragma unroll
        for (int j = 0; j < 8; j++) acc[r][j] = 0.f;
    tile_phase(pb + OFF_KOUT, 64, 64, h + (size_t)b*NF*HWD, n0, As, Bs, acc);
    tile_phase(pb + OFF_KSK, FIN, FIN, feat + (size_t)b*FIN*HWD, n0, As, Bs, acc);
    int tm = threadIdx.x & 15, tn = threadIdx.x >> 4;
    #pragma unroll
    for (int r = 0; r < 4; r++){
        int m = tm*4 + r;
        float bias = pb[OFF_BOUT + m] + pb[OFF_BSK + m];
        float* dst = outp + ((size_t)b*NF + m)*HWD + n0 + tn*8;
        float4 v0, v1;
        v0.x = acc[r][0]+bias; v0.y = acc[r][1]+bias;
        v0.z = acc[r][2]+bias; v0.w = acc[r][3]+bias;
        v1.x = acc[r][4]+bias; v1.y = acc[r][5]+bias;
        v1.z = acc[r][6]+bias; v1.w = acc[r][7]+bias;
        *(float4*)dst = v0; *(float4*)(dst+4) = v1;
    }
}

// ---------------- freq = (out . pe) / 4096 into cat[:, 512:] ----------------
__global__ void __launch_bounds__(128) k_freq(const float* __restrict__ out,
                                              const float* __restrict__ pe,
                                              float* __restrict__ cat){
    int b = blockIdx.y;
    int c0 = blockIdx.x*4;
    const float* o0 = out + ((size_t)b*NF + c0)*HWD;
    float acc[4][24];
    #pragma unroll
    for (int ch = 0; ch < 4; ch++)
        #pragma unroll
        for (int f = 0; f < 24; f++) acc[ch][f] = 0.f;
    for (int p = threadIdx.x; p < HWD; p += 128){
        float ov0 = o0[p], ov1 = o0[HWD+p], ov2 = o0[2*HWD+p], ov3 = o0[3*HWD+p];
        #pragma unroll
        for (int f = 0; f < 24; f++){
            float pv = pe[f*HWD + p];
            acc[0][f] += ov0*pv; acc[1][f] += ov1*pv;
            acc[2][f] += ov2*pv; acc[3][f] += ov3*pv;
        }
    }
    __shared__ float red[4][4][24];
    int lane = threadIdx.x & 31, wrp = threadIdx.x >> 5;
    #pragma unroll
    for (int ch = 0; ch < 4; ch++)
        #pragma unroll
        for (int f = 0; f < 24; f++){
            float v = acc[ch][f];
            #pragma unroll
            for (int s = 16; s > 0; s >>= 1) v += __shfl_xor_sync(0xffffffffu, v, s);
            if (lane == 0) red[wrp][ch][f] = v;
        }
    __syncthreads();
    if (threadIdx.x < 96){
        int ch = threadIdx.x / 24, f = threadIdx.x % 24;
        float s = red[0][ch][f] + red[1][ch][f] + red[2][ch][f] + red[3][ch][f];
        cat[b*CATD + 512 + (c0+ch)*24 + f] = s * (1.f/4096.f);
    }
}

// ---------------- host orchestration ----------------
extern "C" void kernel_launch(void* const* d_in, const int* in_sizes, int n_in,
                              void* d_out, int out_size){
    const float* x      = (const float*)d_in[0];
    const float* inj    = (const float*)d_in[1];
    const float* w_in   = (const float*)d_in[2];
    const float* b_in   = (const float*)d_in[3];
    const float* fl_w1  = (const float*)d_in[4];
    const float* fl_b1  = (const float*)d_in[5];
    const float* fl_w2  = (const float*)d_in[6];
    const float* fl_b2  = (const float*)d_in[7];
    const float* fl_ws  = (const float*)d_in[8];
    const float* fl_bs  = (const float*)d_in[9];
    const float* dyn_w  = (const float*)d_in[10];
    const float* dyn_b  = (const float*)d_in[11];
    const float* pe     = (const float*)d_in[12];
    const float* otl_w1 = (const float*)d_in[13];
    const float* otl_b1 = (const float*)d_in[14];
    const float* otl_w2 = (const float*)d_in[15];
    const float* otl_b2 = (const float*)d_in[16];
    const float* otl_ws = (const float*)d_in[17];
    const float* otl_bs = (const float*)d_in[18];
    const float* ltl_w  = (const float*)d_in[19];
    const float* ltl_b  = (const float*)d_in[20];

    float *p_out, *p_feat, *p_h, *p_p, *p_injA, *p_injB, *p_latA, *p_latB;
    float *p_t512, *p_cat, *p_t2048, *p_part;
    cudaGetSymbolAddress((void**)&p_out,  g_out);
    cudaGetSymbolAddress((void**)&p_feat, g_feat);
    cudaGetSymbolAddress((void**)&p_h,    g_h);
    cudaGetSymbolAddress((void**)&p_p,    g_p);
    cudaGetSymbolAddress((void**)&p_injA, g_injA);
    cudaGetSymbolAddress((void**)&p_injB, g_injB);
    cudaGetSymbolAddress((void**)&p_latA, g_latA);
    cudaGetSymbolAddress((void**)&p_latB, g_latB);
    cudaGetSymbolAddress((void**)&p_t512, g_t512);
    cudaGetSymbolAddress((void**)&p_cat,  g_cat);
    cudaGetSymbolAddress((void**)&p_t2048,g_t2048);
    cudaGetSymbolAddress((void**)&p_part, g_part);

    cudaMemcpyAsync(p_injA, inj, (size_t)NB*LATD*sizeof(float), cudaMemcpyDeviceToDevice);
    k_zero<<<16, 512>>>(p_latA);
    k_init_out<<<NB*NF, 256>>>(x, w_in, b_in, p_out);

    float* injC = p_injA; float* injN = p_injB;
    float* latC = p_latA; float* latN = p_latB;

    for (int c = 0; c < 4; c++){
        // inj_lat = lin_res(inj_lat, fl_*)
        gemm16_part<<<dim3(4,8), 128>>>(injC, LATD, fl_w1, p_part, LATD, 64, 0);
        gemm16_reduce<<<32, 256>>>(p_part, 8, fl_b1, nullptr, p_t512, LATD, 1);
        gemm16_part<<<dim3(4,8), 128>>>(injC, LATD, fl_ws, p_part, LATD, 64, 0);
        gemm16_part<<<dim3(4,8), 128>>>(p_t512, LATD, fl_w2, p_part, LATD, 64, 8);
        gemm16_reduce<<<32, 256>>>(p_part, 16, fl_bs, fl_b2, injN, LATD, 0);

        // p = inj_lat @ dyn_w + dyn_b
        gemm16_full<<<(PD + 127)/128, 128>>>(injN, LATD, dyn_w, dyn_b, p_p, PD);

        // feat = inorm(perceive(out))
        k_perceive<<<NB*NF, 256>>>(p_out, p_feat);

        // dynamic conv
        k_gemm_h<<<dim3(32, NB), 256>>>(p_p, p_feat, p_h);
        k_gemm_out<<<dim3(32, NB), 256>>>(p_p, p_h, p_feat, p_out);

        // cat = [lat, freq]
        k_freq<<<dim3(16, NB), 128>>>(p_out, pe, p_cat);
        k_copylat<<<32, 256>>>(latC, p_cat);

        // lat = lin_res(cat, otl_*[c])
        const float* w1 = otl_w1 + (size_t)c*CATD*CATD;
        const float* b1 = otl_b1 + (size_t)c*CATD;
        const float* w2 = otl_w2 + (size_t)c*CATD*LATD;
        const float* b2 = otl_b2 + (size_t)c*LATD;
        const float* ws = otl_ws + (size_t)c*CATD*LATD;
        const float* bs = otl_bs + (size_t)c*LATD;
        gemm16_part<<<dim3(16,8), 128>>>(p_cat, CATD, w1, p_part, CATD, 256, 0);
        gemm16_reduce<<<128, 256>>>(p_part, 8, b1, nullptr, p_t2048, CATD, 1);
        gemm16_part<<<dim3(4,8), 128>>>(p_cat, CATD, ws, p_part, LATD, 256, 0);
        gemm16_part<<<dim3(4,8), 128>>>(p_t2048, CATD, w2, p_part, LATD, 256, 8);
        gemm16_reduce<<<32, 256>>>(p_part, 16, bs, b2, latN, LATD, 0);

        float* t;
        t = injC; injC = injN; injN = t;
        t = latC; latC = latN; latN = t;
    }

    // out = lat @ ltl_w + ltl_b
    gemm16_part<<<dim3(4,8), 128>>>(latC, LATD, ltl_w, p_part, LATD, 64, 0);
    gemm16_reduce<<<32, 256>>>(p_part, 8, ltl_b, nullptr, (float*)d_out, LATD, 0);
}